// round 6
// baseline (speedup 1.0000x reference)
#include <cuda_runtime.h>
#include <cstdint>

#define NB 2
#define NE 10
#define NC 64
#define NH 128
#define NW 256
#define HW (NH*NW)
#define TW 16
#define MPAD 68   // padded row stride for M/P hi-lo tiles (conflict-free A frags)

// Persistent device scratch (no allocations allowed).
__device__ float d_Mr[NC*NC];          // M[c][cp] row-major, M = Wq^T Wk
__device__ float d_Pr[NC*NC];          // P[d][c] row-major,  P = Wo Wv
__device__ float d_s3[NB*NH*NE*NE];    // axis=3 scores->weights [b][h][i][j]
__device__ float d_s4[NB*NW*NE*NE];    // axis=4 scores->weights [b][w][i][j]

typedef unsigned long long u64;

__device__ __forceinline__ u64 pack2(float lo, float hi){
    u64 r; asm("mov.b64 %0, {%1, %2};" : "=l"(r) : "f"(lo), "f"(hi)); return r;
}
__device__ __forceinline__ void fma2(u64 &d, u64 a, u64 b){
    asm("fma.rn.f32x2 %0, %1, %2, %0;" : "+l"(d) : "l"(a), "l"(b));
}
__device__ __forceinline__ float2 unpack2(u64 v){
    float2 r; asm("mov.b64 {%0, %1}, %2;" : "=f"(r.x), "=f"(r.y) : "l"(v)); return r;
}
__device__ __forceinline__ uint32_t cvt_tf32(float f){
    uint32_t u; asm("cvt.rna.tf32.f32 %0, %1;" : "=r"(u) : "f"(f)); return u;
}
__device__ __forceinline__ void mma8(float* C, uint32_t a0, uint32_t a1, uint32_t a2, uint32_t a3,
                                     uint32_t b0, uint32_t b1){
    asm volatile("mma.sync.aligned.m16n8k8.row.col.f32.tf32.tf32.f32 "
                 "{%0,%1,%2,%3}, {%4,%5,%6,%7}, {%8,%9}, {%0,%1,%2,%3};"
                 : "+f"(C[0]), "+f"(C[1]), "+f"(C[2]), "+f"(C[3])
                 : "r"(a0), "r"(a1), "r"(a2), "r"(a3), "r"(b0), "r"(b1));
}

// ---------------- prep (+zero): M = Wq^T Wk, P = Wo Wv, zero s3/s4 ----------------
__global__ void prep_kernel(const float* __restrict__ Wq, const float* __restrict__ Wk,
                            const float* __restrict__ Wv, const float* __restrict__ Wo){
    int idx = blockIdx.x * blockDim.x + threadIdx.x;
    if (idx < NC*NC){
        int c = idx >> 6, cp = idx & 63;               // M[c][cp] = sum_d Wq[d,c]*Wk[d,cp]
        float s = 0.f;
        #pragma unroll 8
        for (int d = 0; d < NC; d++) s += Wq[d*NC + c] * Wk[d*NC + cp];
        d_Mr[idx] = s;
    } else if (idx < 2*NC*NC){
        int t = idx - NC*NC;
        int d = t >> 6, c = t & 63;                    // P[d][c] = sum_e Wo[d,e]*Wv[e,c]
        float s = 0.f;
        #pragma unroll 8
        for (int e = 0; e < NC; e++) s += Wo[d*NC + e] * Wv[e*NC + c];
        d_Pr[t] = s;
    }
    if (idx < NB*NH*NE*NE) d_s3[idx] = 0.f;
    if (idx < NB*NW*NE*NE) d_s4[idx] = 0.f;
}

// ---------------- scores: Y = M X via tf32-mma (3-term), gram scalar fp32 --------------
// smem floats: Xs [NE*NC][16] | Mhi [64][68] | Mlo [64][68] | Ys [2][64][16]
#define SMEM_SCORES ((NE*NC*TW + 2*NC*MPAD + 2*NC*TW)*4)
__global__ void __launch_bounds__(256) scores_kernel(const float* __restrict__ x){
    extern __shared__ float sm[];
    float* Xs  = sm;                          // row = e*64+c, idx = row*16 + w
    float* Mhi = sm + NE*NC*TW;
    float* Mlo = Mhi + NC*MPAD;
    float* Ys  = Mlo + NC*MPAD;               // [jj][c][w] : jj*1024 + c*16 + w

    const int tid = threadIdx.x, lane = tid & 31, warp = tid >> 5;
    const int b = blockIdx.z, h = blockIdx.y, w0 = blockIdx.x * TW;

    for (int i = tid; i < NC*NC; i += 256){
        int r = i >> 6, c = i & 63;
        float m = d_Mr[i];
        float hi = __uint_as_float(cvt_tf32(m));
        Mhi[r*MPAD + c] = hi;
        Mlo[r*MPAD + c] = __uint_as_float(cvt_tf32(m - hi));
    }
    const float* xb = x + (size_t)b*NE*NC*HW + h*NW + w0;
    for (int i = tid; i < NE*NC*(TW/4); i += 256){
        int row = i >> 2, q = i & 3;
        ((float4*)Xs)[i] = *(const float4*)(xb + (size_t)row*HW + q*4);
    }
    __syncthreads();

    const int g  = lane >> 2;                 // 0..7
    const int tg = lane & 3;                  // 0..3
    const int mtile = warp >> 1, npair = warp & 1;
    const int r0 = mtile*16 + g;

    for (int jp = 0; jp < NE; jp += 2){
        // ---- y phase: tensor-core GEMM Y[64 x 32cols], cols n = jj*16 + w
        float C0[4] = {0,0,0,0}, C1[4] = {0,0,0,0};
        #pragma unroll
        for (int k = 0; k < 8; k++){
            int kc = k*8 + tg;
            uint32_t ah0 = __float_as_uint(Mhi[ r0   *MPAD + kc]);
            uint32_t ah1 = __float_as_uint(Mhi[(r0+8)*MPAD + kc]);
            uint32_t ah2 = __float_as_uint(Mhi[ r0   *MPAD + kc + 4]);
            uint32_t ah3 = __float_as_uint(Mhi[(r0+8)*MPAD + kc + 4]);
            uint32_t al0 = __float_as_uint(Mlo[ r0   *MPAD + kc]);
            uint32_t al1 = __float_as_uint(Mlo[(r0+8)*MPAD + kc]);
            uint32_t al2 = __float_as_uint(Mlo[ r0   *MPAD + kc + 4]);
            uint32_t al3 = __float_as_uint(Mlo[(r0+8)*MPAD + kc + 4]);
            #pragma unroll
            for (int t = 0; t < 2; t++){
                int n  = (npair*2 + t)*8 + g;
                int jj = n >> 4, w = n & 15;
                const float* bp = Xs + (size_t)((jp + jj)*NC + kc)*TW + w;
                float f0 = bp[0], f1 = bp[4*TW];
                uint32_t bh0 = cvt_tf32(f0);
                uint32_t bl0 = cvt_tf32(f0 - __uint_as_float(bh0));
                uint32_t bh1 = cvt_tf32(f1);
                uint32_t bl1 = cvt_tf32(f1 - __uint_as_float(bh1));
                float* C = t ? C1 : C0;
                mma8(C, ah0,ah1,ah2,ah3, bh0,bh1);
                mma8(C, ah0,ah1,ah2,ah3, bl0,bl1);
                mma8(C, al0,al1,al2,al3, bh0,bh1);
            }
        }
        #pragma unroll
        for (int t = 0; t < 2; t++){
            int n  = (npair*2 + t)*8 + 2*tg;
            int jj = n >> 4, w = n & 15;
            float* C = t ? C1 : C0;
            Ys[jj*1024 +  r0   *TW + w    ] = C[0];
            Ys[jj*1024 +  r0   *TW + w + 1] = C[1];
            Ys[jj*1024 + (r0+8)*TW + w    ] = C[2];
            Ys[jj*1024 + (r0+8)*TW + w + 1] = C[3];
        }
        __syncthreads();

        // ---- g phase (scalar fp32): thread=(i,w), 160 active
        if (tid < NE*TW){
            const int gi = tid >> 4, gw = tid & 15;
            u64 g0 = 0, g1 = 0;
            const float* xi = Xs + (size_t)gi*NC*TW + gw;
            const float* y0 = Ys + gw;
            const float* y1 = Ys + 1024 + gw;
            #pragma unroll 8
            for (int p = 0; p < 32; p++){
                u64 xp  = pack2(xi[(2*p)*TW], xi[(2*p+1)*TW]);
                u64 yp0 = pack2(y0[(2*p)*TW], y0[(2*p+1)*TW]);
                u64 yp1 = pack2(y1[(2*p)*TW], y1[(2*p+1)*TW]);
                fma2(g0, xp, yp0);
                fma2(g1, xp, yp1);
            }
            float2 f0 = unpack2(g0), f1 = unpack2(g1);
            float s0 = f0.x + f0.y, s1 = f1.x + f1.y;
            float* s4p = &d_s4[((b*NW + w0 + gw)*NE + gi)*NE + jp];
            atomicAdd(s4p,     s0);
            atomicAdd(s4p + 1, s1);
            #pragma unroll
            for (int off = 8; off; off >>= 1){
                s0 += __shfl_down_sync(0xffffffffu, s0, off, 16);
                s1 += __shfl_down_sync(0xffffffffu, s1, off, 16);
            }
            if (gw == 0){
                float* s3p = &d_s3[((b*NH + h)*NE + gi)*NE + jp];
                atomicAdd(s3p,     s0);
                atomicAdd(s3p + 1, s1);
            }
        }
        __syncthreads();
    }
}

// ---------------- softmax over j (in place), with the per-axis scale ----------------
__global__ void softmax_kernel(){
    int idx = blockIdx.x * blockDim.x + threadIdx.x;
    float* row; float scale;
    if (idx < NB*NH*NE){ row = d_s3 + idx*NE; scale = 1.0f/128.0f; }            // 1/sqrt(64*256)
    else {
        int r = idx - NB*NH*NE;
        if (r >= NB*NW*NE) return;
        row = d_s4 + r*NE; scale = rsqrtf(64.0f*128.0f);                         // 1/sqrt(64*128)
    }
    float v[NE], m = -3.4e38f;
    #pragma unroll
    for (int j = 0; j < NE; j++){ v[j] = row[j]*scale; m = fmaxf(m, v[j]); }
    float s = 0.f;
    #pragma unroll
    for (int j = 0; j < NE; j++){ v[j] = expf(v[j] - m); s += v[j]; }
    float inv = 1.0f/s;
    #pragma unroll
    for (int j = 0; j < NE; j++) row[j] = v[j]*inv;
}

// ---------------- output: z scalar; y = P z via tf32-mma (3-term); gelu(2x+y) ------
// smem floats: Xs | Phi [64][68] | Plo | Zs [2][64][16] | w3s[128] | w4s[16][100]
#define SMEM_OUT ((NE*NC*TW + 2*NC*MPAD + 2*NC*TW + 128 + TW*NE*NE)*4)
__global__ void __launch_bounds__(256) output_kernel(const float* __restrict__ x,
                                                     float* __restrict__ out){
    extern __shared__ float sm[];
    float* Xs  = sm;
    float* Phi = sm + NE*NC*TW;
    float* Plo = Phi + NC*MPAD;
    float* Zs  = Plo + NC*MPAD;               // [ii][c][w] : ii*1024 + c*16 + w
    float* w3s = Zs + 2*NC*TW;                // 128 slots (100 used)
    float* w4s = w3s + 128;                   // [w][NE*NE]

    const int tid = threadIdx.x, lane = tid & 31, warp = tid >> 5;
    const int b = blockIdx.z, h = blockIdx.y, w0 = blockIdx.x * TW;
    const int wpos = lane & 15, half = lane >> 4;

    for (int i = tid; i < NC*NC; i += 256){
        int r = i >> 6, c = i & 63;
        float p = d_Pr[i];
        float hi = __uint_as_float(cvt_tf32(p));
        Phi[r*MPAD + c] = hi;
        Plo[r*MPAD + c] = __uint_as_float(cvt_tf32(p - hi));
    }
    if (tid < NE*NE) w3s[tid] = d_s3[(b*NH + h)*NE*NE + tid];
    for (int t = tid; t < TW*NE*NE; t += 256)
        w4s[t] = d_s4[(size_t)(b*NW + w0)*NE*NE + t];

    const float* xb = x + (size_t)b*NE*NC*HW + h*NW + w0;
    for (int i = tid; i < NE*NC*(TW/4); i += 256){
        int row = i >> 2, q = i & 3;
        ((float4*)Xs)[i] = *(const float4*)(xb + (size_t)row*HW + q*4);
    }
    __syncthreads();

    const int g  = lane >> 2, tg = lane & 3;
    const int mtile = warp >> 1, npair = warp & 1;
    const int r0 = mtile*16 + g;
    const int cc = warp*8 + half*4;           // z-phase: 4 channels per lane
    const float* w4r = w4s + wpos*NE*NE;

    for (int ip = 0; ip < NE; ip += 2){
        const int i0 = ip, i1 = ip + 1;
        // ---- z phase (scalar fp32): z[cc..cc+3][wpos] for i0,i1
        u64 z00=0, z01=0, z10=0, z11=0;
        #pragma unroll
        for (int j = 0; j < NE; j++){
            float c_0 = w3s[i0*NE + j] + w4r[i0*NE + j];
            float c_1 = w3s[i1*NE + j] + w4r[i1*NE + j];
            u64 cw0 = pack2(c_0, c_0), cw1 = pack2(c_1, c_1);
            const float* xj = Xs + (size_t)j*NC*TW + cc*TW + wpos;
            u64 xv0 = pack2(xj[0*TW], xj[1*TW]);
            u64 xv1 = pack2(xj[2*TW], xj[3*TW]);
            fma2(z00, xv0, cw0); fma2(z01, xv1, cw0);
            fma2(z10, xv0, cw1); fma2(z11, xv1, cw1);
        }
        { float2 t;
          t = unpack2(z00); Zs[(cc  )*TW + wpos] = t.x; Zs[(cc+1)*TW + wpos] = t.y;
          t = unpack2(z01); Zs[(cc+2)*TW + wpos] = t.x; Zs[(cc+3)*TW + wpos] = t.y;
          t = unpack2(z10); Zs[1024 + (cc  )*TW + wpos] = t.x; Zs[1024 + (cc+1)*TW + wpos] = t.y;
          t = unpack2(z11); Zs[1024 + (cc+2)*TW + wpos] = t.x; Zs[1024 + (cc+3)*TW + wpos] = t.y; }
        __syncthreads();

        // ---- y phase: tensor-core GEMM y = P z, cols n = ii*16 + w
        float C0[4] = {0,0,0,0}, C1[4] = {0,0,0,0};
        #pragma unroll
        for (int k = 0; k < 8; k++){
            int kc = k*8 + tg;
            uint32_t ah0 = __float_as_uint(Phi[ r0   *MPAD + kc]);
            uint32_t ah1 = __float_as_uint(Phi[(r0+8)*MPAD + kc]);
            uint32_t ah2 = __float_as_uint(Phi[ r0   *MPAD + kc + 4]);
            uint32_t ah3 = __float_as_uint(Phi[(r0+8)*MPAD + kc + 4]);
            uint32_t al0 = __float_as_uint(Plo[ r0   *MPAD + kc]);
            uint32_t al1 = __float_as_uint(Plo[(r0+8)*MPAD + kc]);
            uint32_t al2 = __float_as_uint(Plo[ r0   *MPAD + kc + 4]);
            uint32_t al3 = __float_as_uint(Plo[(r0+8)*MPAD + kc + 4]);
            #pragma unroll
            for (int t = 0; t < 2; t++){
                int n  = (npair*2 + t)*8 + g;
                int ii = n >> 4, w = n & 15;
                const float* bp = Zs + (size_t)(ii*NC + kc)*TW + w;
                float f0 = bp[0], f1 = bp[4*TW];
                uint32_t bh0 = cvt_tf32(f0);
                uint32_t bl0 = cvt_tf32(f0 - __uint_as_float(bh0));
                uint32_t bh1 = cvt_tf32(f1);
                uint32_t bl1 = cvt_tf32(f1 - __uint_as_float(bh1));
                float* C = t ? C1 : C0;
                mma8(C, ah0,ah1,ah2,ah3, bh0,bh1);
                mma8(C, ah0,ah1,ah2,ah3, bl0,bl1);
                mma8(C, al0,al1,al2,al3, bh0,bh1);
            }
        }
        // ---- epilogue: gelu(2x + y), direct float2 stores
        #pragma unroll
        for (int t = 0; t < 2; t++){
            int n  = (npair*2 + t)*8 + 2*tg;
            int ii = n >> 4, w = n & 15;
            int i  = ip + ii;
            float* C = t ? C1 : C0;
            #pragma unroll
            for (int rr = 0; rr < 2; rr++){
                int d = r0 + rr*8;
                const float* xp = Xs + (size_t)(i*NC + d)*TW + w;
                float v0 = C[rr*2 + 0] + 2.f*xp[0];
                float v1 = C[rr*2 + 1] + 2.f*xp[1];
                float g0 = 0.5f*v0*(1.0f + tanhf(0.7978845608028654f*(v0 + 0.044715f*v0*v0*v0)));
                float g1 = 0.5f*v1*(1.0f + tanhf(0.7978845608028654f*(v1 + 0.044715f*v1*v1*v1)));
                float2 o = make_float2(g0, g1);
                *(float2*)(out + ((size_t)(b*NE + i)*NC + d)*HW + h*NW + w0 + w) = o;
            }
        }
        __syncthreads();   // Zs reused next pair
    }
}

// ---------------- launch ----------------
extern "C" void kernel_launch(void* const* d_in, const int* in_sizes, int n_in,
                              void* d_out, int out_size){
    const float* x  = (const float*)d_in[0];
    const float* Wv = (const float*)d_in[1];
    const float* Wk = (const float*)d_in[2];
    const float* Wq = (const float*)d_in[3];
    const float* Wo = (const float*)d_in[4];
    float* out = (float*)d_out;

    cudaFuncSetAttribute(scores_kernel, cudaFuncAttributeMaxDynamicSharedMemorySize, SMEM_SCORES);
    cudaFuncSetAttribute(output_kernel, cudaFuncAttributeMaxDynamicSharedMemorySize, SMEM_OUT);

    prep_kernel<<<(NB*NW*NE*NE + 255)/256, 256>>>(Wq, Wk, Wv, Wo);

    dim3 grid(NW/TW, NH, NB);
    scores_kernel<<<grid, 256, SMEM_SCORES>>>(x);
    softmax_kernel<<<(NB*NH*NE + NB*NW*NE + 255)/256, 256>>>();
    output_kernel<<<grid, 256, SMEM_OUT>>>(x, out);
}

// round 7
// speedup vs baseline: 1.1046x; 1.1046x over previous
#include <cuda_runtime.h>
#include <cstdint>

#define NB 2
#define NE 10
#define NC 64
#define NH 128
#define NW 256
#define HW (NH*NW)
#define TW 16
#define CS 68          // channel-row stride (floats), padded: conflict-free LDS.128
#define ES (TW*CS)     // ensemble stride = 1088 floats
#define MPAD 68        // M/P tile row stride

// Persistent device scratch (no allocations allowed).
__device__ float d_Mr[NC*NC];          // M[c][cp] row-major, M = Wq^T Wk
__device__ float d_Pr[NC*NC];          // P[d][c] row-major,  P = Wo Wv
__device__ float d_s3[NB*NH*NE*NE];    // axis=3 scores->weights [b][h][i][j]
__device__ float d_s4[NB*NW*NE*NE];    // axis=4 scores->weights [b][w][i][j]

__device__ __forceinline__ uint32_t cvt_tf32(float f){
    uint32_t u; asm("cvt.rna.tf32.f32 %0, %1;" : "=r"(u) : "f"(f)); return u;
}
__device__ __forceinline__ void mma8(float* C, uint32_t a0, uint32_t a1, uint32_t a2, uint32_t a3,
                                     uint32_t b0, uint32_t b1){
    asm volatile("mma.sync.aligned.m16n8k8.row.col.f32.tf32.tf32.f32 "
                 "{%0,%1,%2,%3}, {%4,%5,%6,%7}, {%8,%9}, {%0,%1,%2,%3};"
                 : "+f"(C[0]), "+f"(C[1]), "+f"(C[2]), "+f"(C[3])
                 : "r"(a0), "r"(a1), "r"(a2), "r"(a3), "r"(b0), "r"(b1));
}

// ---------------- prep (+zero): M = Wq^T Wk, P = Wo Wv, zero s3/s4 ----------------
__global__ void prep_kernel(const float* __restrict__ Wq, const float* __restrict__ Wk,
                            const float* __restrict__ Wv, const float* __restrict__ Wo){
    int idx = blockIdx.x * blockDim.x + threadIdx.x;
    if (idx < NC*NC){
        int c = idx >> 6, cp = idx & 63;
        float s = 0.f;
        #pragma unroll 8
        for (int d = 0; d < NC; d++) s += Wq[d*NC + c] * Wk[d*NC + cp];
        d_Mr[idx] = s;
    } else if (idx < 2*NC*NC){
        int t = idx - NC*NC;
        int d = t >> 6, c = t & 63;
        float s = 0.f;
        #pragma unroll 8
        for (int e = 0; e < NC; e++) s += Wo[d*NC + e] * Wv[e*NC + c];
        d_Pr[t] = s;
    }
    if (idx < NB*NH*NE*NE) d_s3[idx] = 0.f;
    if (idx < NB*NW*NE*NE) d_s4[idx] = 0.f;
}

// ---- shared helpers for tile loading (channel-contiguous layout) ----
__device__ __forceinline__ void load_x_tile(float* Xs, const float* xb, int tid){
    // Xs[e][w][c] = x[e,c, h, w0+w]; gmem float4 over w, scattered STS over c
    for (int i = tid; i < NE*NC*(TW/4); i += 256){
        int row = i >> 2, q = i & 3;            // row = e*64+c
        float4 v = *(const float4*)(xb + (size_t)row*HW + q*4);
        int e = row >> 6, c = row & 63;
        float* dst = Xs + (size_t)e*ES + (q*4)*CS + c;
        dst[0]    = v.x; dst[CS]   = v.y;
        dst[2*CS] = v.z; dst[3*CS] = v.w;
    }
}
__device__ __forceinline__ void split_w_tile(float* Whi, float* Wlo, const float* Wsrc, int tid){
    for (int i = tid; i < NC*NC; i += 256){
        int r = i >> 6, c = i & 63;
        float m = Wsrc[i];
        float hi = __uint_as_float(cvt_tf32(m));
        Whi[r*MPAD + c] = hi;
        Wlo[r*MPAD + c] = __uint_as_float(cvt_tf32(m - hi));
    }
}
#define LOAD_A_FRAGS(Ah, Al, Hi, Lo, r0, tg)                                     \
    _Pragma("unroll")                                                            \
    for (int k = 0; k < 8; k++){                                                 \
        int kc = k*8 + (tg);                                                     \
        Ah[k][0] = __float_as_uint(Hi[ (r0)   *MPAD + kc    ]);                  \
        Ah[k][1] = __float_as_uint(Hi[((r0)+8)*MPAD + kc    ]);                  \
        Ah[k][2] = __float_as_uint(Hi[ (r0)   *MPAD + kc + 4]);                  \
        Ah[k][3] = __float_as_uint(Hi[((r0)+8)*MPAD + kc + 4]);                  \
        Al[k][0] = __float_as_uint(Lo[ (r0)   *MPAD + kc    ]);                  \
        Al[k][1] = __float_as_uint(Lo[((r0)+8)*MPAD + kc    ]);                  \
        Al[k][2] = __float_as_uint(Lo[ (r0)   *MPAD + kc + 4]);                  \
        Al[k][3] = __float_as_uint(Lo[((r0)+8)*MPAD + kc + 4]);                  \
    }
// 3-term compensated tf32 mma against smem B at (base + w*CS + kc), b1 at +4
#define MMA3(C, k, Bbase)                                                        \
    {   const float* bp = (Bbase);                                               \
        float f0 = bp[0], f1 = bp[4];                                            \
        uint32_t bh0 = cvt_tf32(f0);                                             \
        uint32_t bl0 = cvt_tf32(f0 - __uint_as_float(bh0));                      \
        uint32_t bh1 = cvt_tf32(f1);                                             \
        uint32_t bl1 = cvt_tf32(f1 - __uint_as_float(bh1));                      \
        mma8(C, Ah[k][0],Ah[k][1],Ah[k][2],Ah[k][3], bh0,bh1);                   \
        mma8(C, Ah[k][0],Ah[k][1],Ah[k][2],Ah[k][3], bl0,bl1);                   \
        mma8(C, Al[k][0],Al[k][1],Al[k][2],Al[k][3], bh0,bh1);                   \
    }

// ---------------- scores: Y = M X (tf32 mma, A in regs), gram via LDS.128 ----------------
// smem floats: Xs [NE][16][68] | Mhi [64][68] | Mlo | Ys [2][16][68]
#define SMEM_SCORES ((NE*ES + 2*NC*MPAD + 2*ES)*4)
__global__ void __launch_bounds__(256) scores_kernel(const float* __restrict__ x){
    extern __shared__ float sm[];
    float* Xs  = sm;
    float* Mhi = sm + NE*ES;
    float* Mlo = Mhi + NC*MPAD;
    float* Ys  = Mlo + NC*MPAD;               // [jj][w][c]

    const int tid = threadIdx.x, lane = tid & 31, warp = tid >> 5;
    const int b = blockIdx.z, h = blockIdx.y, w0 = blockIdx.x * TW;

    split_w_tile(Mhi, Mlo, d_Mr, tid);
    load_x_tile(Xs, x + (size_t)b*NE*NC*HW + h*NW + w0, tid);
    __syncthreads();

    const int g = lane >> 2, tg = lane & 3;
    const int mtile = warp >> 1, npair = warp & 1;
    const int r0 = mtile*16 + g;

    uint32_t Ah[8][4], Al[8][4];
    LOAD_A_FRAGS(Ah, Al, Mhi, Mlo, r0, tg)

    for (int jp = 0; jp < NE; jp += 2){
        // ---- y phase: Y[64 x (2*16)] = M * X[jp..jp+1]
        float C0[4] = {0,0,0,0}, C1[4] = {0,0,0,0};
        const int n0 = (npair*2    )*8 + g;
        const int n1 = (npair*2 + 1)*8 + g;
        const float* B0 = Xs + (size_t)(jp + (n0 >> 4))*ES + (n0 & 15)*CS;
        const float* B1 = Xs + (size_t)(jp + (n1 >> 4))*ES + (n1 & 15)*CS;
        #pragma unroll
        for (int k = 0; k < 8; k++){
            int kc = k*8 + tg;
            MMA3(C0, k, B0 + kc)
            MMA3(C1, k, B1 + kc)
        }
        #pragma unroll
        for (int t = 0; t < 2; t++){
            int n  = (npair*2 + t)*8 + 2*tg;
            float* yb = Ys + (size_t)(n >> 4)*ES + (n & 15)*CS;
            float* C = t ? C1 : C0;
            yb[r0]          = C[0];
            yb[CS + r0]     = C[1];
            yb[r0 + 8]      = C[2];
            yb[CS + r0 + 8] = C[3];
        }
        __syncthreads();

        // ---- g phase: thread=(i,w), 160 active; all loads LDS.128 conflict-free
        if (tid < NE*TW){
            const int gi = tid >> 4, gw = tid & 15;
            const float4* xi = (const float4*)(Xs + (size_t)gi*ES + gw*CS);
            const float4* y0 = (const float4*)(Ys + gw*CS);
            const float4* y1 = (const float4*)(Ys + ES + gw*CS);
            float s0 = 0.f, s1 = 0.f;
            #pragma unroll
            for (int m = 0; m < 16; m++){
                float4 xv = xi[m], a = y0[m], c2 = y1[m];
                s0 = fmaf(xv.x, a.x, s0);  s0 = fmaf(xv.y, a.y, s0);
                s0 = fmaf(xv.z, a.z, s0);  s0 = fmaf(xv.w, a.w, s0);
                s1 = fmaf(xv.x, c2.x, s1); s1 = fmaf(xv.y, c2.y, s1);
                s1 = fmaf(xv.z, c2.z, s1); s1 = fmaf(xv.w, c2.w, s1);
            }
            float* s4p = &d_s4[((b*NW + w0 + gw)*NE + gi)*NE + jp];
            atomicAdd(s4p,     s0);
            atomicAdd(s4p + 1, s1);
            #pragma unroll
            for (int off = 8; off; off >>= 1){
                s0 += __shfl_down_sync(0xffffffffu, s0, off, 16);
                s1 += __shfl_down_sync(0xffffffffu, s1, off, 16);
            }
            if (gw == 0){
                float* s3p = &d_s3[((b*NH + h)*NE + gi)*NE + jp];
                atomicAdd(s3p,     s0);
                atomicAdd(s3p + 1, s1);
            }
        }
        __syncthreads();
    }
}

// ---------------- softmax over j (in place), with the per-axis scale ----------------
__global__ void softmax_kernel(){
    int idx = blockIdx.x * blockDim.x + threadIdx.x;
    float* row; float scale;
    if (idx < NB*NH*NE){ row = d_s3 + idx*NE; scale = 1.0f/128.0f; }
    else {
        int r = idx - NB*NH*NE;
        if (r >= NB*NW*NE) return;
        row = d_s4 + r*NE; scale = rsqrtf(64.0f*128.0f);
    }
    float v[NE], m = -3.4e38f;
    #pragma unroll
    for (int j = 0; j < NE; j++){ v[j] = row[j]*scale; m = fmaxf(m, v[j]); }
    float s = 0.f;
    #pragma unroll
    for (int j = 0; j < NE; j++){ v[j] = expf(v[j] - m); s += v[j]; }
    float inv = 1.0f/s;
    #pragma unroll
    for (int j = 0; j < NE; j++) row[j] = v[j]*inv;
}

// ---------------- output: z (LDS.128 scalar) ; y = P z (tf32 mma, A in regs); gelu ----
// smem floats: Xs | Phi | Plo | Zs [2][16][68] | w3s[128] | w4s[16][100]
#define SMEM_OUT ((NE*ES + 2*NC*MPAD + 2*ES + 128 + TW*NE*NE)*4)
__global__ void __launch_bounds__(256) output_kernel(const float* __restrict__ x,
                                                     float* __restrict__ out){
    extern __shared__ float sm[];
    float* Xs  = sm;
    float* Phi = sm + NE*ES;
    float* Plo = Phi + NC*MPAD;
    float* Zs  = Plo + NC*MPAD;               // [ii][w][c]
    float* w3s = Zs + 2*ES;
    float* w4s = w3s + 128;                   // [w][NE*NE]

    const int tid = threadIdx.x, lane = tid & 31, warp = tid >> 5;
    const int b = blockIdx.z, h = blockIdx.y, w0 = blockIdx.x * TW;

    split_w_tile(Phi, Plo, d_Pr, tid);
    if (tid < NE*NE) w3s[tid] = d_s3[(b*NH + h)*NE*NE + tid];
    for (int t = tid; t < TW*NE*NE; t += 256)
        w4s[t] = d_s4[(size_t)(b*NW + w0)*NE*NE + t];
    load_x_tile(Xs, x + (size_t)b*NE*NC*HW + h*NW + w0, tid);
    __syncthreads();

    const int g = lane >> 2, tg = lane & 3;
    const int mtile = warp >> 1, npair = warp & 1;
    const int r0 = mtile*16 + g;
    const int zw = tid >> 4, cq = (tid & 15)*4;      // z-phase: thread=(w, c-quad)
    const float* w4r = w4s + zw*NE*NE;

    uint32_t Ah[8][4], Al[8][4];
    LOAD_A_FRAGS(Ah, Al, Phi, Plo, r0, tg)

    for (int ip = 0; ip < NE; ip += 2){
        // ---- z phase: z[i0,i1][zw][cq..cq+3], all LDS.128
        float4 z0 = make_float4(0,0,0,0), z1 = make_float4(0,0,0,0);
        #pragma unroll
        for (int j = 0; j < NE; j++){
            float c_0 = w3s[ip*NE + j]     + w4r[ip*NE + j];
            float c_1 = w3s[(ip+1)*NE + j] + w4r[(ip+1)*NE + j];
            float4 xv = *(const float4*)(Xs + (size_t)j*ES + zw*CS + cq);
            z0.x = fmaf(c_0, xv.x, z0.x); z0.y = fmaf(c_0, xv.y, z0.y);
            z0.z = fmaf(c_0, xv.z, z0.z); z0.w = fmaf(c_0, xv.w, z0.w);
            z1.x = fmaf(c_1, xv.x, z1.x); z1.y = fmaf(c_1, xv.y, z1.y);
            z1.z = fmaf(c_1, xv.z, z1.z); z1.w = fmaf(c_1, xv.w, z1.w);
        }
        *(float4*)(Zs +      zw*CS + cq) = z0;
        *(float4*)(Zs + ES + zw*CS + cq) = z1;
        __syncthreads();

        // ---- y phase: y = P z for both halves of the i-pair
        float C0[4] = {0,0,0,0}, C1[4] = {0,0,0,0};
        const int n0 = (npair*2    )*8 + g;
        const int n1 = (npair*2 + 1)*8 + g;
        const float* B0 = Zs + (size_t)(n0 >> 4)*ES + (n0 & 15)*CS;
        const float* B1 = Zs + (size_t)(n1 >> 4)*ES + (n1 & 15)*CS;
        #pragma unroll
        for (int k = 0; k < 8; k++){
            int kc = k*8 + tg;
            MMA3(C0, k, B0 + kc)
            MMA3(C1, k, B1 + kc)
        }

        // ---- epilogue: gelu(2x + y), float2 stores (w contiguous)
        #pragma unroll
        for (int t = 0; t < 2; t++){
            int n  = (npair*2 + t)*8 + 2*tg;
            int ii = n >> 4, w = n & 15;
            int i  = ip + ii;
            float* C = t ? C1 : C0;
            #pragma unroll
            for (int rr = 0; rr < 2; rr++){
                int d = r0 + rr*8;
                float xp0 = Xs[(size_t)i*ES +  w   *CS + d];
                float xp1 = Xs[(size_t)i*ES + (w+1)*CS + d];
                float v0 = C[rr*2 + 0] + 2.f*xp0;
                float v1 = C[rr*2 + 1] + 2.f*xp1;
                float g0 = 0.5f*v0*(1.0f + tanhf(0.7978845608028654f*(v0 + 0.044715f*v0*v0*v0)));
                float g1 = 0.5f*v1*(1.0f + tanhf(0.7978845608028654f*(v1 + 0.044715f*v1*v1*v1)));
                *(float2*)(out + ((size_t)(b*NE + i)*NC + d)*HW + h*NW + w0 + w)
                    = make_float2(g0, g1);
            }
        }
        __syncthreads();   // Zs reused next pair
    }
}

// ---------------- launch ----------------
extern "C" void kernel_launch(void* const* d_in, const int* in_sizes, int n_in,
                              void* d_out, int out_size){
    const float* x  = (const float*)d_in[0];
    const float* Wv = (const float*)d_in[1];
    const float* Wk = (const float*)d_in[2];
    const float* Wq = (const float*)d_in[3];
    const float* Wo = (const float*)d_in[4];
    float* out = (float*)d_out;

    cudaFuncSetAttribute(scores_kernel, cudaFuncAttributeMaxDynamicSharedMemorySize, SMEM_SCORES);
    cudaFuncSetAttribute(output_kernel, cudaFuncAttributeMaxDynamicSharedMemorySize, SMEM_OUT);

    prep_kernel<<<(NB*NW*NE*NE + 255)/256, 256>>>(Wq, Wk, Wv, Wo);

    dim3 grid(NW/TW, NH, NB);
    scores_kernel<<<grid, 256, SMEM_SCORES>>>(x);
    softmax_kernel<<<(NB*NH*NE + NB*NW*NE + 255)/256, 256>>>();
    output_kernel<<<grid, 256, SMEM_OUT>>>(x, out);
}

// round 9
// speedup vs baseline: 1.1484x; 1.0397x over previous
#include <cuda_runtime.h>
#include <cstdint>

#define NB 2
#define NE 10
#define NC 64
#define NH 128
#define NW 256
#define HW (NH*NW)
#define TW 16
#define CS 68          // channel-row stride (floats), padded: conflict-free LDS.128
#define ES (TW*CS)     // ensemble stride = 1088 floats
#define MPAD 68        // M/P tile row stride

// Persistent device scratch (no allocations allowed).
__device__ float d_Mr[NC*NC];          // M[c][cp] row-major, M = Wq^T Wk
__device__ float d_Pr[NC*NC];          // P[d][c] row-major,  P = Wo Wv
__device__ float d_s3[NB*NH*NE*NE];    // axis=3 scores->weights [b][h][i][j]
__device__ float d_s4[NB*NW*NE*NE];    // axis=4 scores->weights [b][w][i][j]

__device__ __forceinline__ uint32_t cvt_tf32(float f){
    uint32_t u; asm("cvt.rna.tf32.f32 %0, %1;" : "=r"(u) : "f"(f)); return u;
}
__device__ __forceinline__ void mma8(float* C, uint32_t a0, uint32_t a1, uint32_t a2, uint32_t a3,
                                     uint32_t b0, uint32_t b1){
    asm volatile("mma.sync.aligned.m16n8k8.row.col.f32.tf32.tf32.f32 "
                 "{%0,%1,%2,%3}, {%4,%5,%6,%7}, {%8,%9}, {%0,%1,%2,%3};"
                 : "+f"(C[0]), "+f"(C[1]), "+f"(C[2]), "+f"(C[3])
                 : "r"(a0), "r"(a1), "r"(a2), "r"(a3), "r"(b0), "r"(b1));
}
__device__ __forceinline__ float gelu(float t){
    return 0.5f*t*(1.0f + tanhf(0.7978845608028654f*(t + 0.044715f*t*t*t)));
}

// ---------------- prep (+zero): M = Wq^T Wk, P = Wo Wv, zero s3/s4 ----------------
__global__ void prep_kernel(const float* __restrict__ Wq, const float* __restrict__ Wk,
                            const float* __restrict__ Wv, const float* __restrict__ Wo){
    int idx = blockIdx.x * blockDim.x + threadIdx.x;
    if (idx < NC*NC){
        int c = idx >> 6, cp = idx & 63;
        float s = 0.f;
        #pragma unroll 8
        for (int d = 0; d < NC; d++) s += Wq[d*NC + c] * Wk[d*NC + cp];
        d_Mr[idx] = s;
    } else if (idx < 2*NC*NC){
        int t = idx - NC*NC;
        int d = t >> 6, c = t & 63;
        float s = 0.f;
        #pragma unroll 8
        for (int e = 0; e < NC; e++) s += Wo[d*NC + e] * Wv[e*NC + c];
        d_Pr[t] = s;
    }
    if (idx < NB*NH*NE*NE) d_s3[idx] = 0.f;
    if (idx < NB*NW*NE*NE) d_s4[idx] = 0.f;
}

// ---- shared helpers for tile loading (channel-contiguous layout) ----
__device__ __forceinline__ void load_x_tile(float* Xs, const float* xb, int tid){
    for (int i = tid; i < NE*NC*(TW/4); i += 256){
        int row = i >> 2, q = i & 3;            // row = e*64+c
        float4 v = *(const float4*)(xb + (size_t)row*HW + q*4);
        int e = row >> 6, c = row & 63;
        float* dst = Xs + (size_t)e*ES + (q*4)*CS + c;
        dst[0]    = v.x; dst[CS]   = v.y;
        dst[2*CS] = v.z; dst[3*CS] = v.w;
    }
}
__device__ __forceinline__ void split_w_tile(float* Whi, float* Wlo, const float* Wsrc, int tid){
    for (int i = tid; i < NC*NC; i += 256){
        int r = i >> 6, c = i & 63;
        float m = Wsrc[i];
        float hi = __uint_as_float(cvt_tf32(m));
        Whi[r*MPAD + c] = hi;
        Wlo[r*MPAD + c] = __uint_as_float(cvt_tf32(m - hi));
    }
}
#define LOAD_A_FRAGS(Ah, Al, Hi, Lo, r0, tg)                                     \
    _Pragma("unroll")                                                            \
    for (int k = 0; k < 8; k++){                                                 \
        int kc = k*8 + (tg);                                                     \
        Ah[k][0] = __float_as_uint(Hi[ (r0)   *MPAD + kc    ]);                  \
        Ah[k][1] = __float_as_uint(Hi[((r0)+8)*MPAD + kc    ]);                  \
        Ah[k][2] = __float_as_uint(Hi[ (r0)   *MPAD + kc + 4]);                  \
        Ah[k][3] = __float_as_uint(Hi[((r0)+8)*MPAD + kc + 4]);                  \
        Al[k][0] = __float_as_uint(Lo[ (r0)   *MPAD + kc    ]);                  \
        Al[k][1] = __float_as_uint(Lo[((r0)+8)*MPAD + kc    ]);                  \
        Al[k][2] = __float_as_uint(Lo[ (r0)   *MPAD + kc + 4]);                  \
        Al[k][3] = __float_as_uint(Lo[((r0)+8)*MPAD + kc + 4]);                  \
    }
#define MMA3(C, k, Bbase)                                                        \
    {   const float* bp = (Bbase);                                               \
        float f0 = bp[0], f1 = bp[4];                                            \
        uint32_t bh0 = cvt_tf32(f0);                                             \
        uint32_t bl0 = cvt_tf32(f0 - __uint_as_float(bh0));                      \
        uint32_t bh1 = cvt_tf32(f1);                                             \
        uint32_t bl1 = cvt_tf32(f1 - __uint_as_float(bh1));                      \
        mma8(C, Ah[k][0],Ah[k][1],Ah[k][2],Ah[k][3], bh0,bh1);                   \
        mma8(C, Ah[k][0],Ah[k][1],Ah[k][2],Ah[k][3], bl0,bl1);                   \
        mma8(C, Al[k][0],Al[k][1],Al[k][2],Al[k][3], bh0,bh1);                   \
    }

// ---------------- scores: Y = M X (tf32 mma, A in regs), gram via LDS.128 ---------------
// smem floats: Xs [NE][16][68] | Mhi [64][68] | Mlo | Ys DOUBLE-BUFFERED [2][2][16][68]
#define SMEM_SCORES ((NE*ES + 2*NC*MPAD + 4*ES)*4)
__global__ void __launch_bounds__(256, 2) scores_kernel(const float* __restrict__ x){
    extern __shared__ float sm[];
    float* Xs  = sm;
    float* Mhi = sm + NE*ES;
    float* Mlo = Mhi + NC*MPAD;
    float* Ys  = Mlo + NC*MPAD;               // [buf][jj][w][c]

    const int tid = threadIdx.x, lane = tid & 31, warp = tid >> 5;
    const int b = blockIdx.z, h = blockIdx.y, w0 = blockIdx.x * TW;

    split_w_tile(Mhi, Mlo, d_Mr, tid);
    load_x_tile(Xs, x + (size_t)b*NE*NC*HW + h*NW + w0, tid);
    __syncthreads();

    const int g = lane >> 2, tg = lane & 3;
    const int mtile = warp >> 1, npair = warp & 1;
    const int r0 = mtile*16 + g;

    uint32_t Ah[8][4], Al[8][4];
    LOAD_A_FRAGS(Ah, Al, Mhi, Mlo, r0, tg)

    for (int jp = 0; jp < NE; jp += 2){
        float* Yb = Ys + ((jp >> 1) & 1) * 2*ES;
        // ---- y phase: Y[64 x (2*16)] = M * X[jp..jp+1]
        float C0[4] = {0,0,0,0}, C1[4] = {0,0,0,0};
        const int n0 = (npair*2    )*8 + g;
        const int n1 = (npair*2 + 1)*8 + g;
        const float* B0 = Xs + (size_t)(jp + (n0 >> 4))*ES + (n0 & 15)*CS;
        const float* B1 = Xs + (size_t)(jp + (n1 >> 4))*ES + (n1 & 15)*CS;
        #pragma unroll
        for (int k = 0; k < 8; k++){
            int kc = k*8 + tg;
            MMA3(C0, k, B0 + kc)
            MMA3(C1, k, B1 + kc)
        }
        #pragma unroll
        for (int t = 0; t < 2; t++){
            int n  = (npair*2 + t)*8 + 2*tg;
            float* yb = Yb + (size_t)(n >> 4)*ES + (n & 15)*CS;
            float* C = t ? C1 : C0;
            yb[r0]          = C[0];
            yb[CS + r0]     = C[1];
            yb[r0 + 8]      = C[2];
            yb[CS + r0 + 8] = C[3];
        }
        __syncthreads();     // single barrier per jp (double-buffered Ys)

        // ---- g phase: thread=(i,w), 160 active; all loads LDS.128 conflict-free
        if (tid < NE*TW){
            const int gi = tid >> 4, gw = tid & 15;
            const float4* xi = (const float4*)(Xs + (size_t)gi*ES + gw*CS);
            const float4* y0 = (const float4*)(Yb + gw*CS);
            const float4* y1 = (const float4*)(Yb + ES + gw*CS);
            float s0 = 0.f, s1 = 0.f;
            #pragma unroll
            for (int m = 0; m < 16; m++){
                float4 xv = xi[m], a = y0[m], c2 = y1[m];
                s0 = fmaf(xv.x, a.x, s0);  s0 = fmaf(xv.y, a.y, s0);
                s0 = fmaf(xv.z, a.z, s0);  s0 = fmaf(xv.w, a.w, s0);
                s1 = fmaf(xv.x, c2.x, s1); s1 = fmaf(xv.y, c2.y, s1);
                s1 = fmaf(xv.z, c2.z, s1); s1 = fmaf(xv.w, c2.w, s1);
            }
            float* s4p = &d_s4[((b*NW + w0 + gw)*NE + gi)*NE + jp];
            atomicAdd(s4p,     s0);
            atomicAdd(s4p + 1, s1);
            #pragma unroll
            for (int off = 8; off; off >>= 1){
                s0 += __shfl_down_sync(0xffffffffu, s0, off, 16);
                s1 += __shfl_down_sync(0xffffffffu, s1, off, 16);
            }
            if (gw == 0){
                float* s3p = &d_s3[((b*NH + h)*NE + gi)*NE + jp];
                atomicAdd(s3p,     s0);
                atomicAdd(s3p + 1, s1);
            }
        }
        // no trailing barrier: buffer for this jp is only rewritten at jp+4,
        // and the barrier after jp+2's mma-store orders that reuse.
    }
}

// ---------------- softmax over j (in place), with the per-axis scale ----------------
__global__ void softmax_kernel(){
    int idx = blockIdx.x * blockDim.x + threadIdx.x;
    float* row; float scale;
    if (idx < NB*NH*NE){ row = d_s3 + idx*NE; scale = 1.0f/128.0f; }
    else {
        int r = idx - NB*NH*NE;
        if (r >= NB*NW*NE) return;
        row = d_s4 + r*NE; scale = rsqrtf(64.0f*128.0f);
    }
    float v[NE], m = -3.4e38f;
    #pragma unroll
    for (int j = 0; j < NE; j++){ v[j] = row[j]*scale; m = fmaxf(m, v[j]); }
    float s = 0.f;
    #pragma unroll
    for (int j = 0; j < NE; j++){ v[j] = expf(v[j] - m); s += v[j]; }
    float inv = 1.0f/s;
    #pragma unroll
    for (int j = 0; j < NE; j++) row[j] = v[j]*inv;
}

// ---------------- output: U = P X (one tile-wide GEMM, U stays in C-frags), ----------
// ---------------- then out_i = gelu(sum_j cw_ij U_j + 2 x_i) all in registers --------
// smem floats: Xs [NE][16][68] | Phi | Plo | w3s[128] | w4s[16][100]   (~85 KB)
#define SMEM_OUT ((NE*ES + 2*NC*MPAD + 128 + TW*NE*NE)*4)
__global__ void __launch_bounds__(256, 2) output_kernel(const float* __restrict__ x,
                                                        float* __restrict__ out){
    extern __shared__ float sm[];
    float* Xs  = sm;
    float* Phi = sm + NE*ES;
    float* Plo = Phi + NC*MPAD;
    float* w3s = Plo + NC*MPAD;               // 128 slots (100 used)
    float* w4s = w3s + 128;                   // [w][NE*NE]

    const int tid = threadIdx.x, lane = tid & 31, warp = tid >> 5;
    const int b = blockIdx.z, h = blockIdx.y, w0 = blockIdx.x * TW;

    split_w_tile(Phi, Plo, d_Pr, tid);
    if (tid < NE*NE) w3s[tid] = d_s3[(b*NH + h)*NE*NE + tid];
    for (int t = tid; t < TW*NE*NE; t += 256)
        w4s[t] = d_s4[(size_t)(b*NW + w0)*NE*NE + t];
    load_x_tile(Xs, x + (size_t)b*NE*NC*HW + h*NW + w0, tid);
    __syncthreads();                          // the ONLY barrier in this kernel

    const int g = lane >> 2, tg = lane & 3;
    const int whalf = warp >> 2, mtile = warp & 3;
    const int r0   = mtile*16 + g;            // C rows r0, r0+8
    const int wcol = whalf*8 + g;             // B column (w) this thread feeds
    const int wa   = whalf*8 + 2*tg;          // C columns wa, wa+1

    // U = P * X  — all 10 ensembles' C-fragments in registers
    float C[NE][4];
    #pragma unroll
    for (int e = 0; e < NE; e++){ C[e][0]=0.f; C[e][1]=0.f; C[e][2]=0.f; C[e][3]=0.f; }

    #pragma unroll
    for (int k = 0; k < 8; k++){
        const int kc = k*8 + tg;
        uint32_t Ahk[4], Alk[4];
        Ahk[0] = __float_as_uint(Phi[ r0   *MPAD + kc    ]);
        Ahk[1] = __float_as_uint(Phi[(r0+8)*MPAD + kc    ]);
        Ahk[2] = __float_as_uint(Phi[ r0   *MPAD + kc + 4]);
        Ahk[3] = __float_as_uint(Phi[(r0+8)*MPAD + kc + 4]);
        Alk[0] = __float_as_uint(Plo[ r0   *MPAD + kc    ]);
        Alk[1] = __float_as_uint(Plo[(r0+8)*MPAD + kc    ]);
        Alk[2] = __float_as_uint(Plo[ r0   *MPAD + kc + 4]);
        Alk[3] = __float_as_uint(Plo[(r0+8)*MPAD + kc + 4]);
        #pragma unroll
        for (int e = 0; e < NE; e++){
            const float* bp = Xs + (size_t)e*ES + wcol*CS + kc;
            float f0 = bp[0], f1 = bp[4];
            uint32_t bh0 = cvt_tf32(f0);
            uint32_t bl0 = cvt_tf32(f0 - __uint_as_float(bh0));
            uint32_t bh1 = cvt_tf32(f1);
            uint32_t bl1 = cvt_tf32(f1 - __uint_as_float(bh1));
            mma8(C[e], Ahk[0],Ahk[1],Ahk[2],Ahk[3], bh0,bh1);
            mma8(C[e], Ahk[0],Ahk[1],Ahk[2],Ahk[3], bl0,bl1);
            mma8(C[e], Alk[0],Alk[1],Alk[2],Alk[3], bh0,bh1);
        }
    }

    // combine + residual + gelu, entirely from registers / scalar smem
    const float* w4a = w4s + (size_t) wa   *NE*NE;
    const float* w4b = w4s + (size_t)(wa+1)*NE*NE;
    #pragma unroll
    for (int i = 0; i < NE; i++){
        const float* xi = Xs + (size_t)i*ES;
        float a0 = 2.f*xi[ wa   *CS + r0    ];
        float a1 = 2.f*xi[(wa+1)*CS + r0    ];
        float a2 = 2.f*xi[ wa   *CS + r0 + 8];
        float a3 = 2.f*xi[(wa+1)*CS + r0 + 8];
        #pragma unroll
        for (int j = 0; j < NE; j++){
            float w3v = w3s[i*NE + j];
            float cwa = w3v + w4a[i*NE + j];
            float cwb = w3v + w4b[i*NE + j];
            a0 = fmaf(cwa, C[j][0], a0);
            a1 = fmaf(cwb, C[j][1], a1);
            a2 = fmaf(cwa, C[j][2], a2);
            a3 = fmaf(cwb, C[j][3], a3);
        }
        float* op = out + ((size_t)(b*NE + i)*NC + r0)*HW + h*NW + w0 + wa;
        *(float2*)op            = make_float2(gelu(a0), gelu(a1));
        *(float2*)(op + 8*HW)   = make_float2(gelu(a2), gelu(a3));
    }
}

// ---------------- launch ----------------
extern "C" void kernel_launch(void* const* d_in, const int* in_sizes, int n_in,
                              void* d_out, int out_size){
    const float* x  = (const float*)d_in[0];
    const float* Wv = (const float*)d_in[1];
    const float* Wk = (const float*)d_in[2];
    const float* Wq = (const float*)d_in[3];
    const float* Wo = (const float*)d_in[4];
    float* out = (float*)d_out;

    cudaFuncSetAttribute(scores_kernel, cudaFuncAttributeMaxDynamicSharedMemorySize, SMEM_SCORES);
    cudaFuncSetAttribute(output_kernel, cudaFuncAttributeMaxDynamicSharedMemorySize, SMEM_OUT);

    prep_kernel<<<(NB*NW*NE*NE + 255)/256, 256>>>(Wq, Wk, Wv, Wo);

    dim3 grid(NW/TW, NH, NB);
    scores_kernel<<<grid, 256, SMEM_SCORES>>>(x);
    softmax_kernel<<<(NB*NH*NE + NB*NW*NE + 255)/256, 256>>>();
    output_kernel<<<grid, 256, SMEM_OUT>>>(x, out);
}